// round 16
// baseline (speedup 1.0000x reference)
#include <cuda_runtime.h>
#include <math.h>
#include <stdint.h>

// ===========================================================================
// EncoderAttention3 via mma.sync tf32 (m16n8k8), register accumulators.
// R13: R12 + scalar-overhead cuts: ss pre-rounded to tf32 at neighbor-sum
//      (kills 128 redundant cvts/thread in GEMM3), table-driven X assembly,
//      2-fma LayerNorm form, div-free ego copy. Mainloop untouched. 2 CTAs/SM.
// ===========================================================================

namespace {
constexpr int OBS_DIM = 216, EGO = 48, NEIGH = 7, H = 256, DOUT = 64, OUT_DIM = 112;
constexpr int BATCHES = 16384;
constexpr int BPB     = 8;
constexpr int RVALID  = BPB * NEIGH;   // 56
constexpr int M       = 64;
constexpr int K1      = 80;            // padded 73 -> 80 (5 chunks of 16)
constexpr int THREADS = 256;
constexpr int CH      = 16;
constexpr int NC1     = K1 / CH;       // 5
constexpr int NC2     = H / CH;        // 16
constexpr int XS      = 80;            // X row stride  (320 B; mod 128 == 64)
constexpr int H1S     = 272;           // h1 row stride (1088 B; mod 128 == 64)
constexpr int BUFSZ   = CH * H;        // 4096 floats per 16-k weight chunk [n][16]
constexpr int W3B     = CH * DOUT;     // 1024 floats per 16-k W3 block [n][16]
constexpr int SSS     = 264;           // ss row stride (conflict-free lq dim)

// smem layout (float offsets)
constexpr int B1C = 0;                 // 256
constexpr int GC  = 256;               // 256
constexpr int BBC = 512;               // 256
constexpr int B2C = 768;               // 256
constexpr int B3C = 1024;              // 64
constexpr int PSU = 1088;              // [4][64]
constexpr int PSQ = 1344;              // [4][64]
constexpr int H1O = 1600;              // h1 [64][272]  (X [64][80] aliases this)
constexpr int XO  = H1O;
constexpr int SSO = H1O + M * H1S;     // 19008: ss [8][264] (kpos layout, tf32 bits)
constexpr int SMEM_FLOATS = SSO + BPB * SSS;   // 21120
constexpr int SMEM_BYTES  = SMEM_FLOATS * 4;   // 84480 (2 CTAs/SM)
}  // namespace

// weight images, 16-float k-block layout:
//   [n][pos], pos = 4*lr + 2*ks + hh  ->  k = block*16 + ks*8 + lr + 4*hh
__device__ float g_w1[NC1 * BUFSZ];
__device__ float g_w2[NC2 * BUFSZ];
__device__ float g_w3[NC2 * W3B];
// X source table, indexed by PHYSICAL column position:
//   >=1000: obs[enc-1000+n]; >=0: obs[enc]; -1: team id; -2: zero pad
__device__ int g_xsrc[K1];

// ---------------------------------------------------------------------------
__device__ __forceinline__ uint32_t tf32r(float f) {
    uint32_t u;
    asm("cvt.rna.tf32.f32 %0, %1;" : "=r"(u) : "f"(f));
    return u;
}
__device__ __forceinline__ float tanha(float x) {
    float y;
    asm("tanh.approx.f32 %0, %1;" : "=f"(y) : "f"(x));
    return y;
}
__device__ __forceinline__ void cp16(uint32_t dst, const void* src) {
    asm volatile("cp.async.cg.shared.global [%0], [%1], 16;" :: "r"(dst), "l"(src));
}
#define CP_COMMIT() asm volatile("cp.async.commit_group;" ::: "memory")
#define CP_WAIT0()  asm volatile("cp.async.wait_group 0;" ::: "memory")

__device__ __forceinline__ void mma8(float d[4], const uint32_t a[4],
                                     uint32_t b0, uint32_t b1) {
    asm volatile("mma.sync.aligned.m16n8k8.row.col.f32.tf32.tf32.f32 "
                 "{%0,%1,%2,%3},{%4,%5,%6,%7},{%8,%9},{%0,%1,%2,%3};"
                 : "+f"(d[0]), "+f"(d[1]), "+f"(d[2]), "+f"(d[3])
                 : "r"(a[0]), "r"(a[1]), "r"(a[2]), "r"(a[3]), "r"(b0), "r"(b1));
}

// logical k-in-block (0..15) -> physical position in the 16-float block
__device__ __forceinline__ int kpos(int km) {
    return 4 * (km & 3) + 2 * (km >> 3) + ((km >> 2) & 1);
}

// one 16-k chunk: A (smem, LDS.128, k-block layout), B (global, LDG.128, L1)
__device__ __forceinline__ void gemm_chunk16(const float* __restrict__ A, int as, int k0,
                                             const float4* __restrict__ Bg,
                                             float d[2][8][4], int rb, int cb,
                                             int lq, int lr) {
    uint32_t a[2][2][4];   // [t][ks][frag]
#pragma unroll
    for (int t = 0; t < 2; ++t) {
        const float* ap = A + (rb + t * 16 + lq) * as + k0 + 4 * lr;
        const float4 v0 = *(const float4*)ap;             // row lq
        const float4 v1 = *(const float4*)(ap + 8 * as);  // row lq+8
        a[t][0][0] = __float_as_uint(v0.x); a[t][0][1] = __float_as_uint(v1.x);
        a[t][0][2] = __float_as_uint(v0.y); a[t][0][3] = __float_as_uint(v1.y);
        a[t][1][0] = __float_as_uint(v0.z); a[t][1][1] = __float_as_uint(v1.z);
        a[t][1][2] = __float_as_uint(v0.w); a[t][1][3] = __float_as_uint(v1.w);
    }
    const float4* bb = Bg + (cb + lq) * 4 + lr;
#pragma unroll
    for (int j = 0; j < 8; ++j) {
        const float4 bv = __ldg(bb + j * 32);
        const uint32_t b00 = __float_as_uint(bv.x), b01 = __float_as_uint(bv.y);
        const uint32_t b10 = __float_as_uint(bv.z), b11 = __float_as_uint(bv.w);
        mma8(d[0][j], a[0][0], b00, b01);
        mma8(d[1][j], a[1][0], b00, b01);
        mma8(d[0][j], a[0][1], b10, b11);
        mma8(d[1][j], a[1][1], b10, b11);
    }
}

// ---------------------------------------------------------------------------
__global__ void prep_kernel(const float* __restrict__ W1, const float* __restrict__ W2,
                            const float* __restrict__ W3) {
    const int idx = blockIdx.x * blockDim.x + threadIdx.x;
    const int T1 = NC1 * BUFSZ;
    const int T2 = NC2 * BUFSZ;
    const int T3 = NC2 * W3B;
    if (idx < T1 + T2) {
        const bool w1 = idx < T1;
        const int i2 = w1 ? idx : idx - T1;
        const int chunk = i2 / BUFSZ;
        const int rem   = i2 - chunk * BUFSZ;
        const int n   = rem >> 4;
        const int pos = rem & 15;
        const int lr = pos >> 2, ks = (pos >> 1) & 1, hh = pos & 1;
        const int k  = chunk * CH + ks * 8 + lr + 4 * hh;
        float v = 0.0f;
        if (w1) { if (k < 73) v = W1[k * H + n]; }
        else                  v = W2[k * H + n];
        (w1 ? g_w1 : g_w2)[i2] = __uint_as_float(tf32r(v));
    } else if (idx < T1 + T2 + T3) {
        const int i3 = idx - T1 - T2;
        const int kb  = i3 >> 10;          // / W3B
        const int rem = i3 & (W3B - 1);
        const int n   = rem >> 4;
        const int pos = rem & 15;
        const int lr = pos >> 2, ks = (pos >> 1) & 1, hh = pos & 1;
        const int k  = kb * CH + ks * 8 + lr + 4 * hh;
        g_w3[i3] = __uint_as_float(tf32r(W3[k * DOUT + n]));
    } else if (idx < T1 + T2 + T3 + K1) {
        const int c = idx - T1 - T2 - T3;   // logical column 0..79
        int enc;
        if (c < EGO)      enc = c;
        else if (c < 72)  enc = 1000 + EGO + (c - EGO) * NEIGH;
        else if (c == 72) enc = -1;
        else              enc = -2;
        g_xsrc[(c & ~15) + kpos(c & 15)] = enc;
    }
}

// ---------------------------------------------------------------------------
__global__ void __launch_bounds__(THREADS, 2)
enc3_mma_kernel(const float* __restrict__ obs,
                const float* __restrict__ b1, const float* __restrict__ ln_g,
                const float* __restrict__ ln_b, const float* __restrict__ b2,
                const float* __restrict__ b3,
                float* __restrict__ out)
{
    extern __shared__ float sm[];
    const int tid  = threadIdx.x;
    const int wid  = tid >> 5;
    const int lane = tid & 31;
    const int lq   = lane >> 2, lr = lane & 3;
    const int rb   = (wid >> 2) * 32;    // 2 row groups of 32 rows
    const int cb   = (wid & 3) * 64;     // 4 col groups of 64 cols
    const int b0   = blockIdx.x * BPB;
    const uint32_t smu = (uint32_t)__cvta_generic_to_shared(sm);

    // ---- const vectors via cp.async ----------------------------------------
    {
        if (tid < 64)        cp16(smu + B1C * 4 + tid * 16, (const float4*)b1 + tid);
        else if (tid < 128)  cp16(smu + GC  * 4 + (tid - 64) * 16, (const float4*)ln_g + (tid - 64));
        else if (tid < 192)  cp16(smu + BBC * 4 + (tid - 128) * 16, (const float4*)ln_b + (tid - 128));
        else                 cp16(smu + B2C * 4 + (tid - 192) * 16, (const float4*)b2 + (tid - 192));
        if (tid < 16)        cp16(smu + B3C * 4 + tid * 16, (const float4*)b3 + tid);
        CP_COMMIT();
    }

    // ---- assemble X (tf32, k-block layout): table-driven, 4 threads/row -----
    {
        const int r = tid >> 2, sub = tid & 3;
        const int bl = r / NEIGH;
        const int n  = r - bl * NEIGH;
        const float* ob = obs + (size_t)(b0 + bl) * OBS_DIM;
        const bool valid = (r < RVALID);
#pragma unroll
        for (int p = sub * 20; p < sub * 20 + 20; ++p) {
            const int s = __ldg(g_xsrc + p);
            float v = 0.0f;
            if (valid) {
                if (s >= 1000)    v = ob[s - 1000 + n];
                else if (s >= 0)  v = ob[s];
                else if (s == -1) v = (n >= 3) ? 1.0f : 0.0f;
            }
            sm[XO + r * XS + p] = __uint_as_float(tf32r(v));
        }
    }
    // ---- ego passthrough: 96 float4 copies, div-free-ish --------------------
    if (tid < 96) {
        const int bb = tid / 12, f = tid - bb * 12;
        ((float4*)(out + (size_t)(b0 + bb) * OUT_DIM))[f] =
            ((const float4*)(obs + (size_t)(b0 + bb) * OBS_DIM))[f];
    }

    CP_WAIT0();
    __syncthreads();   // X + consts visible block-wide

    float d[2][8][4];
#pragma unroll
    for (int t = 0; t < 2; ++t)
#pragma unroll
        for (int j = 0; j < 8; ++j)
#pragma unroll
            for (int e = 0; e < 4; ++e) d[t][j][e] = 0.0f;

    // ---- GEMM1: 5 chunks, no barriers (B via LDG/L1) ------------------------
#pragma unroll
    for (int c = 0; c < NC1; ++c)
        gemm_chunk16(sm + XO, XS, c * CH, (const float4*)(g_w1 + c * BUFSZ),
                     d, rb, cb, lq, lr);

    // ---- epilogue 1: +b1, LayerNorm (2-fma form), tanh -> h1 ----------------
    {
        float s[2][2] = {{0.f, 0.f}, {0.f, 0.f}};
        float q[2][2] = {{0.f, 0.f}, {0.f, 0.f}};
#pragma unroll
        for (int t = 0; t < 2; ++t)
#pragma unroll
            for (int j = 0; j < 8; ++j)
#pragma unroll
                for (int e = 0; e < 4; ++e) {
                    const float v = d[t][j][e] + sm[B1C + cb + j * 8 + lr * 2 + (e & 1)];
                    d[t][j][e] = v;
                    s[t][e >> 1] += v;
                    q[t][e >> 1] = fmaf(v, v, q[t][e >> 1]);
                }
#pragma unroll
        for (int t = 0; t < 2; ++t)
#pragma unroll
            for (int h = 0; h < 2; ++h)
#pragma unroll
                for (int o = 1; o < 4; o <<= 1) {
                    s[t][h] += __shfl_xor_sync(0xffffffffu, s[t][h], o);
                    q[t][h] += __shfl_xor_sync(0xffffffffu, q[t][h], o);
                }
        if (lr == 0) {
#pragma unroll
            for (int t = 0; t < 2; ++t)
#pragma unroll
                for (int h = 0; h < 2; ++h) {
                    const int r = rb + t * 16 + h * 8 + lq;
                    sm[PSU + (wid & 3) * 64 + r] = s[t][h];
                    sm[PSQ + (wid & 3) * 64 + r] = q[t][h];
                }
        }
        __syncthreads();
        float rs[2][2], nmr[2][2];
#pragma unroll
        for (int t = 0; t < 2; ++t)
#pragma unroll
            for (int h = 0; h < 2; ++h) {
                const int r = rb + t * 16 + h * 8 + lq;
                const float ts = sm[PSU + r] + sm[PSU + 64 + r] + sm[PSU + 128 + r] + sm[PSU + 192 + r];
                const float tq = sm[PSQ + r] + sm[PSQ + 64 + r] + sm[PSQ + 128 + r] + sm[PSQ + 192 + r];
                const float mu  = ts * (1.0f / 256.0f);
                const float var = fmaf(tq, 1.0f / 256.0f, -mu * mu);
                rs[t][h]  = rsqrtf(var + 1e-5f);
                nmr[t][h] = -mu * rs[t][h];
            }
        __syncthreads();   // all warps done reading X before h1 overwrites region
#pragma unroll
        for (int t = 0; t < 2; ++t)
#pragma unroll
            for (int j = 0; j < 8; ++j)
#pragma unroll
                for (int e = 0; e < 4; ++e) {
                    const int h = e >> 1;
                    const int r = rb + t * 16 + h * 8 + lq;
                    const int col = cb + j * 8 + lr * 2 + (e & 1);          // logical
                    const int phys = (col & ~15) + kpos(col & 15);          // k-block
                    const float z = fmaf(d[t][j][e], rs[t][h], nmr[t][h]);
                    const float y = tanha(fmaf(z, sm[GC + col], sm[BBC + col]));
                    sm[H1O + r * H1S + phys] = __uint_as_float(tf32r(y));
                    d[t][j][e] = 0.0f;
                }
    }
    __syncthreads();   // h1 visible block-wide before GEMM2

    // ---- GEMM2: 16 chunks, no barriers (B via LDG/L1) -----------------------
#pragma unroll 4
    for (int c = 0; c < NC2; ++c)
        gemm_chunk16(sm + H1O, H1S, c * CH, (const float4*)(g_w2 + c * BUFSZ),
                     d, rb, cb, lq, lr);
    __syncthreads();   // all warps done reading h1 before epilogue 2 overwrites

    // ---- epilogue 2: +b2, ELU -> h2 (kpos layout, h1 region) ----------------
#pragma unroll
    for (int t = 0; t < 2; ++t)
#pragma unroll
        for (int j = 0; j < 8; ++j)
#pragma unroll
            for (int e = 0; e < 4; ++e) {
                const int h = e >> 1;
                const int r = rb + t * 16 + h * 8 + lq;
                const int col = cb + j * 8 + lr * 2 + (e & 1);
                const int phys = (col & ~15) + kpos(col & 15);
                float v = d[t][j][e] + sm[B2C + col];
                v = (v > 0.0f) ? v : (__expf(v) - 1.0f);
                sm[H1O + r * H1S + phys] = v;
            }
    __syncthreads();

    // ---- neighbor-sum -> ss[8][264] (kpos layout, PRE-ROUNDED tf32 bits) ----
    {
        const int b = tid >> 5, c0 = (tid & 31) * 8;
        float4 a0 = make_float4(0.f, 0.f, 0.f, 0.f);
        float4 a1 = make_float4(0.f, 0.f, 0.f, 0.f);
        const float* base = sm + H1O + (b * NEIGH) * H1S + c0;
#pragma unroll
        for (int n = 0; n < NEIGH; ++n) {
            const float4 u0 = *(const float4*)(base + n * H1S);
            const float4 u1 = *(const float4*)(base + n * H1S + 4);
            a0.x += u0.x; a0.y += u0.y; a0.z += u0.z; a0.w += u0.w;
            a1.x += u1.x; a1.y += u1.y; a1.z += u1.z; a1.w += u1.w;
        }
        uint4* dst = (uint4*)(sm + SSO + b * SSS + c0);
        dst[0] = make_uint4(tf32r(a0.x), tf32r(a0.y), tf32r(a0.z), tf32r(a0.w));
        dst[1] = make_uint4(tf32r(a1.x), tf32r(a1.y), tf32r(a1.z), tf32r(a1.w));
    }
    __syncthreads();

    // ---- GEMM3 via mma: [16(8 valid) x 256] @ W3 -> [8 x 64] ----------------
    {
        float dc[4] = {0.f, 0.f, 0.f, 0.f};
        const uint32_t* ssr = (const uint32_t*)(sm + SSO + lq * SSS) + lr * 4;
        const float4*   w3p = (const float4*)(g_w3 + (wid * 8 + lq) * 16 + lr * 4);
#pragma unroll
        for (int kb = 0; kb < NC2; ++kb) {
            const uint4  av = *(const uint4*)(ssr + kb * 16);
            const float4 bv = __ldg(w3p + kb * (W3B / 4));
            const uint32_t a0[4] = {av.x, 0u, av.y, 0u};
            const uint32_t a1[4] = {av.z, 0u, av.w, 0u};
            mma8(dc, a0, __float_as_uint(bv.x), __float_as_uint(bv.y));
            mma8(dc, a1, __float_as_uint(bv.z), __float_as_uint(bv.w));
        }
        const int oc = wid * 8 + 2 * lr;
        float* orow = out + (size_t)(b0 + lq) * OUT_DIM + EGO + oc;
        orow[0] = dc[0] + sm[B3C + oc];
        orow[1] = dc[1] + sm[B3C + oc + 1];
    }
}

extern "C" void kernel_launch(void* const* d_in, const int* in_sizes, int n_in,
                              void* d_out, int out_size)
{
    (void)in_sizes; (void)n_in; (void)out_size;
    const float* obs  = (const float*)d_in[0];
    const float* W1   = (const float*)d_in[1];
    const float* b1   = (const float*)d_in[2];
    const float* ln_g = (const float*)d_in[3];
    const float* ln_b = (const float*)d_in[4];
    const float* W2   = (const float*)d_in[5];
    const float* b2   = (const float*)d_in[6];
    const float* W3   = (const float*)d_in[7];
    const float* b3   = (const float*)d_in[8];
    float* out = (float*)d_out;

    const int prep_elems = (NC1 + NC2) * BUFSZ + NC2 * W3B + K1;
    prep_kernel<<<(prep_elems + 255) / 256, 256>>>(W1, W2, W3);

    cudaFuncSetAttribute(enc3_mma_kernel, cudaFuncAttributeMaxDynamicSharedMemorySize, SMEM_BYTES);
    enc3_mma_kernel<<<BATCHES / BPB, THREADS, SMEM_BYTES>>>(
        obs, b1, ln_g, ln_b, b2, b3, out);
}